// round 16
// baseline (speedup 1.0000x reference)
#include <cuda_runtime.h>
#include <cstdint>
#include <math.h>

#define S_TOK 2048
#define HID   2048
#define NJ    24
#define NE    8
#define MAXROWS 5120
#define NTILES  40

#if defined(__CUDA_ARCH__) && defined(__CUDA_ARCH_FEAT_SM103_ALL)
#define HAS_TC 1
#else
#define HAS_TC 0
#endif

// tcgen05 GEMM config: bf16 hi/lo split, KC=64 (128B bf16 rows), 2 stages
#define KC 64
#define NIT (HID / KC)        // 32
#define OFF_AH 0
#define OFF_AL 16384
#define OFF_BH 32768
#define OFF_BL 65536
#define STAGE_SZ 98304        // 96KB
#define SM_CTRL    (2 * STAGE_SZ)      // 196608
#define SM_TMEMPTR (SM_CTRL)
#define SM_DONE    (SM_CTRL + 16)      // 2 x 8B
#define SM_FIN     (SM_CTRL + 32)
#define SM_TOTAL   (SM_CTRL + 64)
#define TCTHREADS 512

// ---------------- device scratch ---------------------------------------------
__device__ float g_mix[S_TOK * NJ];
__device__ int   g_idx[S_TOK * 2];
__device__ float g_score[S_TOK * 2];
__device__ int   g_perm[MAXROWS];
__device__ int   g_slotmap[S_TOK * 2];
__device__ int   g_tile_expert[48];
__device__ int   g_tc_ran;
__device__ int   g_diag;              // 0 tc-ok | 1 wrong | 2 not-ran | 3 zeros
__device__ __align__(256) float g_fc1[(size_t)MAXROWS * 4096];   // fallback only
__device__ __align__(256) float g_inter[(size_t)MAXROWS * 2048]; // fallback only
__device__ __align__(256) float g_y[(size_t)MAXROWS * 2048];
// pre-converted bf16 hi/lo operands (tc path)
__device__ __align__(256) uint16_t g_xh[(size_t)S_TOK * HID];
__device__ __align__(256) uint16_t g_xl[(size_t)S_TOK * HID];
__device__ __align__(256) uint16_t g_w1h[(size_t)NE * 4096 * HID];
__device__ __align__(256) uint16_t g_w1l[(size_t)NE * 4096 * HID];
__device__ __align__(256) uint16_t g_w2h[(size_t)NE * 2048 * HID];
__device__ __align__(256) uint16_t g_w2l[(size_t)NE * 2048 * HID];
__device__ __align__(256) uint16_t g_ih[(size_t)MAXROWS * 2048];
__device__ __align__(256) uint16_t g_il[(size_t)MAXROWS * 2048];

// ---------------- generic helpers --------------------------------------------
__device__ __forceinline__ uint32_t f2tf(float f) {
    uint32_t u; asm("cvt.rna.tf32.f32 %0, %1;" : "=r"(u) : "f"(f)); return u;
}
__device__ __forceinline__ void cp16g(float* dst, const float* src) {
    uint32_t d = (uint32_t)__cvta_generic_to_shared(dst);
    asm volatile("cp.async.cg.shared.global [%0], [%1], 16;\n" :: "r"(d), "l"(src));
}
__device__ __forceinline__ void cpa16(uint32_t dst, uint64_t src) {
    asm volatile("cp.async.cg.shared.global [%0], [%1], 16;\n" :: "r"(dst), "l"(src));
}
#define SWZ128(b) ((b) ^ (((b) >> 3) & 0x70))
#define CPA_COMMIT() asm volatile("cp.async.commit_group;" ::: "memory")
__device__ __forceinline__ uint32_t prmt_hi(uint32_t a, uint32_t b) {
    uint32_t d; asm("prmt.b32 %0, %1, %2, 0x7632;" : "=r"(d) : "r"(a), "r"(b)); return d;
}
__device__ __forceinline__ float losub(float x) {   // exact residual of truncation
    return x - __uint_as_float(__float_as_uint(x) & 0xFFFF0000u);
}
__device__ __forceinline__ uint32_t bf2(float hi, float lo) {
    uint32_t d; asm("cvt.rn.bf16x2.f32 %0, %1, %2;" : "=r"(d) : "f"(hi), "f"(lo)); return d;
}

// ---------------- 0a) X -> bf16 hi/lo ----------------------------------------
__global__ void convx_kernel(const float* __restrict__ X)
{
    size_t i4 = (size_t)blockIdx.x * 256 + threadIdx.x;   // 4M/4 float4s
    float4 v = ((const float4*)X)[i4];
    uint32_t h01 = prmt_hi(__float_as_uint(v.x), __float_as_uint(v.y));
    uint32_t h23 = prmt_hi(__float_as_uint(v.z), __float_as_uint(v.w));
    uint32_t l01 = bf2(losub(v.y), losub(v.x));
    uint32_t l23 = bf2(losub(v.w), losub(v.z));
    ((uint2*)g_xh)[i4] = make_uint2(h01, h23);
    ((uint2*)g_xl)[i4] = make_uint2(l01, l23);
}

// ---------------- 0b) W [e][k][n] fp32 -> hi/lo [e][n][k] bf16 (transpose) ---
__global__ __launch_bounds__(256) void convw_kernel(
    const float* __restrict__ W, uint16_t* __restrict__ Wh,
    uint16_t* __restrict__ Wl, int Nw)
{
    __shared__ float tile[32][33];
    int e = blockIdx.z;
    int n0 = blockIdx.x * 32, k0 = blockIdx.y * 32;
    int tn = threadIdx.x & 31, tr = threadIdx.x >> 5;
    const float* src = W + ((size_t)e * HID + k0) * Nw + n0;
#pragma unroll
    for (int i = 0; i < 4; i++) {
        int k = tr + i * 8;
        tile[k][tn] = src[(size_t)k * Nw + tn];
    }
    __syncthreads();
    size_t dbase = ((size_t)e * Nw + n0) * HID + k0;
#pragma unroll
    for (int i = 0; i < 4; i++) {
        int n = tr + i * 8;
        float v = tile[tn][n];
        uint32_t u = __float_as_uint(v);
        float lo = v - __uint_as_float(u & 0xFFFF0000u);
        Wh[dbase + (size_t)n * HID + tn] = (uint16_t)(u >> 16);
        Wl[dbase + (size_t)n * HID + tn] = (uint16_t)(bf2(0.f, lo) & 0xFFFFu);
    }
}

#if HAS_TC
__device__ __forceinline__ uint32_t smem_u32(const void* p) {
    uint32_t a;
    asm("{ .reg .u64 t; cvta.to.shared.u64 t, %1; cvt.u32.u64 %0, t; }" : "=r"(a) : "l"(p));
    return a;
}
__device__ __forceinline__ uint32_t elect_one() {
    uint32_t p;
    asm volatile("{\n\t.reg .pred p;\n\telect.sync _|p, 0xFFFFFFFF;\n\t"
                 "selp.b32 %0, 1, 0, p;\n\t}" : "=r"(p));
    return p;
}
// K-major SW128 descriptor (verified: test_mma / test_2cta / test_mma_iter)
static __device__ __forceinline__ uint64_t desc_k(uint32_t addr) {
    return ((uint64_t)2 << 61) | ((uint64_t)1 << 46) | ((uint64_t)64 << 32)
         | ((uint64_t)1 << 16) | (uint64_t)((addr >> 4) & 0x3FFF);
}
// VERIFIED idesc (test_mma.cu): F32 acc, bf16 x bf16, M=128, N=32
#define IDESC_BF16 0x8080490u

__device__ __forceinline__ void mma_bf16_ss(uint32_t d, uint64_t ad, uint64_t bd, uint32_t en) {
    asm volatile(
        "{\n\t.reg .pred p;\n\tsetp.ne.u32 p, %4, 0;\n\t"
        "tcgen05.mma.cta_group::1.kind::f16 [%0], %1, %2, %3, {%5, %5, %5, %5}, p;\n\t}"
        :: "r"(d), "l"(ad), "l"(bd), "r"(IDESC_BF16), "r"(en), "r"(0u) : "memory");
}
#define TC_ALLOC(sm, n)  asm volatile("tcgen05.alloc.cta_group::1.sync.aligned.shared::cta.b32 [%0], %1;" :: "r"(sm), "r"(n) : "memory")
#define TC_DEALLOC(t, n) asm volatile("tcgen05.dealloc.cta_group::1.sync.aligned.b32 %0, %1;" :: "r"(t), "r"(n))
#define TC_RELINQ()      asm volatile("tcgen05.relinquish_alloc_permit.cta_group::1.sync.aligned;")
#define TC_COMMIT(mb)    asm volatile("tcgen05.commit.cta_group::1.mbarrier::arrive::one.shared::cluster.b64 [%0];" :: "r"(mb) : "memory")
#define TC_FENCE_AFTER() asm volatile("tcgen05.fence::after_thread_sync;" ::: "memory")
#define TC_WAIT_LD()     asm volatile("tcgen05.wait::ld.sync.aligned;" ::: "memory")
#define FENCE_ASYNC()    asm volatile("fence.proxy.async.shared::cta;" ::: "memory")
#define MBAR_INIT(mb, c) asm volatile("mbarrier.init.shared.b64 [%0], %1;" :: "r"(mb), "r"(c) : "memory")

#define MBAR_WAIT(mb, par) do {                                                  \
    uint32_t _m = (mb), _p = (par), _d = 0;                                      \
    for (int _i = 0; _i < (1 << 22); _i++) {                                     \
        asm volatile("{\n\t.reg .pred p;\n\t"                                    \
            "mbarrier.try_wait.parity.acquire.cta.shared::cta.b64 p, [%1], %2;\n\t" \
            "selp.b32 %0, 1, 0, p;\n\t}" : "=r"(_d) : "r"(_m), "r"(_p) : "memory"); \
        if (_d) break;                                                           \
    }                                                                            \
} while (0)

#define TCLD32(r, a)                                                             \
    asm volatile("tcgen05.ld.sync.aligned.32x32b.x32.b32 "                       \
        "{%0,%1,%2,%3,%4,%5,%6,%7,%8,%9,%10,%11,%12,%13,%14,%15,"                \
        "%16,%17,%18,%19,%20,%21,%22,%23,%24,%25,%26,%27,%28,%29,%30,%31}, [%32];" \
        : "=r"((r)[0]),"=r"((r)[1]),"=r"((r)[2]),"=r"((r)[3]),"=r"((r)[4]),      \
          "=r"((r)[5]),"=r"((r)[6]),"=r"((r)[7]),"=r"((r)[8]),"=r"((r)[9]),      \
          "=r"((r)[10]),"=r"((r)[11]),"=r"((r)[12]),"=r"((r)[13]),"=r"((r)[14]), \
          "=r"((r)[15]),"=r"((r)[16]),"=r"((r)[17]),"=r"((r)[18]),"=r"((r)[19]), \
          "=r"((r)[20]),"=r"((r)[21]),"=r"((r)[22]),"=r"((r)[23]),"=r"((r)[24]), \
          "=r"((r)[25]),"=r"((r)[26]),"=r"((r)[27]),"=r"((r)[28]),"=r"((r)[29]), \
          "=r"((r)[30]),"=r"((r)[31]) : "r"(a))
#endif // HAS_TC

// ---------------- 1) router mix = X @ Wqkv^T ---------------------------------
__global__ __launch_bounds__(256) void gate_kernel(
    const float* __restrict__ X, const float* __restrict__ Wqkv)
{
    __shared__ float xs[128 * 17];
    __shared__ float ws[NJ * 17];
    int t = threadIdx.x;
    int tok0 = blockIdx.x * 128;
    int mgrp = t & 31, jgrp = t >> 5, j0 = jgrp * 3;

    float acc[4][3];
#pragma unroll
    for (int i = 0; i < 4; i++)
#pragma unroll
        for (int j = 0; j < 3; j++) acc[i][j] = 0.f;

    for (int kc = 0; kc < HID; kc += 16) {
#pragma unroll
        for (int i = 0; i < 8; i++) {
            int lin = t + i * 256;
            int m = lin >> 4, k = lin & 15;
            xs[m * 17 + k] = X[(size_t)(tok0 + m) * HID + kc + k];
        }
        for (int lin = t; lin < NJ * 16; lin += 256) {
            int j = lin >> 4, k = lin & 15;
            ws[j * 17 + k] = Wqkv[(size_t)j * HID + kc + k];
        }
        __syncthreads();
#pragma unroll
        for (int k = 0; k < 16; k++) {
            float w0 = ws[(j0 + 0) * 17 + k];
            float w1 = ws[(j0 + 1) * 17 + k];
            float w2 = ws[(j0 + 2) * 17 + k];
#pragma unroll
            for (int i = 0; i < 4; i++) {
                float xv = xs[(mgrp + i * 32) * 17 + k];
                acc[i][0] += xv * w0; acc[i][1] += xv * w1; acc[i][2] += xv * w2;
            }
        }
        __syncthreads();
    }
#pragma unroll
    for (int i = 0; i < 4; i++)
#pragma unroll
        for (int j = 0; j < 3; j++)
            g_mix[(tok0 + mgrp + i * 32) * NJ + j0 + j] = acc[i][j];
}

// ---------------- 2) router attention + top-2 --------------------------------
__global__ void route_kernel()
{
    int s = blockIdx.x * blockDim.x + threadIdx.x;
    if (s >= S_TOK) return;
    float q[NE], kk[NE], v[NE];
#pragma unroll
    for (int i = 0; i < NE; i++) {
        q[i] = g_mix[s * NJ + i]; kk[i] = g_mix[s * NJ + 8 + i]; v[i] = g_mix[s * NJ + 16 + i];
    }
    float logit[NE];
#pragma unroll
    for (int i = 0; i < NE; i++) {
        float mx = -1e30f;
#pragma unroll
        for (int j = 0; j < NE; j++) mx = fmaxf(mx, q[i] * kk[j]);
        float se = 0.f, ac = 0.f;
#pragma unroll
        for (int j = 0; j < NE; j++) {
            float e = expf(q[i] * kk[j] - mx);
            se += e; ac += e * v[j];
        }
        logit[i] = ac / se;
    }
    int i0 = 0;
#pragma unroll
    for (int j = 1; j < NE; j++) if (logit[j] > logit[i0]) i0 = j;
    int i1 = -1;
#pragma unroll
    for (int j = 0; j < NE; j++) {
        if (j == i0) continue;
        if (i1 < 0 || logit[j] > logit[i1]) i1 = j;
    }
    float e1 = expf(logit[i1] - logit[i0]);
    float p0 = 1.f / (1.f + e1);
    g_idx[2 * s] = i0; g_idx[2 * s + 1] = i1;
    g_score[2 * s] = p0; g_score[2 * s + 1] = e1 * p0;
}

// ---------------- 3) stable scatter ------------------------------------------
__global__ void scatter_kernel()
{
    __shared__ int cnt[NE];
    __shared__ int off[NE];
    int t = threadIdx.x, warp = t >> 5, lane = t & 31;

    for (int i = t; i < MAXROWS; i += 256) g_perm[i] = 0;
    if (t < 48) g_tile_expert[t] = -1;
    __syncthreads();

    int c = 0;
    for (int b = 0; b < S_TOK; b += 32) {
        int s = b + lane;
        bool m = (g_idx[2 * s] == warp) || (g_idx[2 * s + 1] == warp);
        c += __popc(__ballot_sync(0xffffffffu, m));
    }
    if (lane == 0) cnt[warp] = c;
    __syncthreads();

    if (t == 0) {
        int rb = 0, tb = 0;
        for (int e = 0; e < NE; e++) {
            off[e] = rb;
            int nt = (cnt[e] + 127) >> 7;
            for (int i = 0; i < nt; i++) g_tile_expert[tb++] = e;
            rb += nt << 7;
        }
    }
    __syncthreads();

    int base = off[warp];
    for (int b = 0; b < S_TOK; b += 32) {
        int s = b + lane;
        bool m0 = (g_idx[2 * s] == warp), m1 = (g_idx[2 * s + 1] == warp);
        bool m = m0 || m1;
        unsigned bal = __ballot_sync(0xffffffffu, m);
        if (m) {
            int pos = base + __popc(bal & ((1u << lane) - 1u));
            g_perm[pos] = s;
            g_slotmap[2 * s + (m0 ? 0 : 1)] = pos;
        }
        base += __popc(bal);
    }
}

// ---------------- 4a) tcgen05 grouped GEMM, pre-converted bf16, cp.async -----
// mode=1: A = g_xh/g_xl via g_perm, B = g_w1h/l [e][n][k], GLU -> g_ih/g_il
// mode=0: A = g_ih/g_il direct, B = g_w2h/l -> g_y (fp32)
__global__ __launch_bounds__(TCTHREADS, 1) __cluster_dims__(1, 1, 1) void moe_gemm_tc(
    int N, int mode, int guarded)
{
#if HAS_TC
    if (guarded && g_diag != 0) return;
    int tile = blockIdx.x;
    int e = g_tile_expert[tile];
    if (tile == 0 && blockIdx.y == 0 && threadIdx.x == 0 && mode) g_tc_ran = 1;
    if (e < 0) return;
    int cb = blockIdx.y;
    int row0 = tile * 128;
    int t = threadIdx.x, wid = t >> 5, lane = t & 31;

    const uint16_t* Ah = mode ? g_xh : g_ih;
    const uint16_t* Al = mode ? g_xl : g_il;
    const uint16_t* Bh = mode ? g_w1h : g_w2h;
    const uint16_t* Bl = mode ? g_w1l : g_w2l;
    int NB = mode ? 4096 : 2048;

    extern __shared__ __align__(1024) char smem[];
    uint32_t smb = smem_u32(smem);

    if (t == 0) {
        MBAR_INIT(smb + SM_DONE + 0, 1);
        MBAR_INIT(smb + SM_DONE + 8, 1);
        MBAR_INIT(smb + SM_FIN, 1);
    }
    if (wid == 0) { TC_ALLOC(smb + SM_TMEMPTR, 256); TC_RELINQ(); }
    __syncthreads();
    uint32_t tmem;
    asm volatile("ld.shared.b32 %0, [%1];" : "=r"(tmem) : "r"(smb + SM_TMEMPTR));

    // ---- per-thread cp.async chunk map: 6144 16B chunks / 512 thr = 12 ----
    uint64_t src[12]; uint32_t dst[12];
#pragma unroll
    for (int i = 0; i < 12; i++) {
        int id = t + i * TCTHREADS;
        if (id < 2048) {                       // A hi (0..1023) / A lo (1024..2047)
            int hl = id >> 10;
            int a = id & 1023;
            int m = a >> 3, c = a & 7;
            int r = mode ? __ldg(&g_perm[row0 + m]) : (row0 + m);
            const uint16_t* base = (hl ? Al : Ah) + (size_t)r * HID;
            src[i] = (uint64_t)base + c * 16;
            dst[i] = (hl ? OFF_AL : OFF_AH) + SWZ128((uint32_t)(m * 128 + c * 16));
        } else {                               // B hi (2048..4095) / B lo (4096..6143)
            int b = id - 2048;
            int hl = b >> 11;
            int bb = b & 2047;
            int r = bb >> 3, c = bb & 7;       // r = 0..255 B-row within tile
            int n = mode ? ((r < 128) ? cb * 128 + r : 2048 + cb * 128 + (r - 128))
                         : (cb * 256 + r);
            const uint16_t* base = (hl ? Bl : Bh) + ((size_t)e * NB + n) * HID;
            src[i] = (uint64_t)base + c * 16;
            dst[i] = (hl ? OFF_BL : OFF_BH) + (r >> 5) * 4096
                   + SWZ128((uint32_t)((r & 31) * 128 + c * 16));
        }
    }

    // prologue: fill stages 0,1 (each its own commit group)
#pragma unroll
    for (int f0 = 0; f0 < 2; f0++) {
        uint32_t base = smb + f0 * STAGE_SZ;
#pragma unroll
        for (int i = 0; i < 12; i++)
            cpa16(base + dst[i], src[i] + (uint64_t)f0 * 128);
        CPA_COMMIT();
    }

    for (int it = 0; it < NIT; it++) {
        int s = it & 1;
        if (it == NIT - 1) asm volatile("cp.async.wait_group 0;" ::: "memory");
        else               asm volatile("cp.async.wait_group 1;" ::: "memory");
        __syncthreads();

        if (wid == 0 && elect_one()) {
            FENCE_ASYNC();
            TC_FENCE_AFTER();
            uint32_t sb = smb + s * STAGE_SZ;
            uint64_t ah = desc_k(sb + OFF_AH), al = desc_k(sb + OFF_AL);
            uint64_t bh = desc_k(sb + OFF_BH), bl = desc_k(sb + OFF_BL);
#pragma unroll
            for (int pp = 0; pp < 8; pp++) {
                uint64_t bhp = bh + pp * 256, blp = bl + pp * 256;
#pragma unroll
                for (int k = 0; k < 4; k++)
                    mma_bf16_ss(tmem + pp * 32, ah + k * 2, bhp + k * 2, (it > 0) || (k > 0));
#pragma unroll
                for (int k = 0; k < 4; k++)
                    mma_bf16_ss(tmem + pp * 32, ah + k * 2, blp + k * 2, 1);
#pragma unroll
                for (int k = 0; k < 4; k++)
                    mma_bf16_ss(tmem + pp * 32, al + k * 2, bhp + k * 2, 1);
            }
            TC_COMMIT(smb + SM_DONE + 8 * s);
            if (it == NIT - 1) TC_COMMIT(smb + SM_FIN);
        }

        int f = it + 2;
        if (f < NIT) {
            // buffer s is being read by MMA(it); wait its completion before refill
            if (t == 0) MBAR_WAIT(smb + SM_DONE + 8 * s, (it >> 1) & 1);
            __syncthreads();
            uint32_t base = smb + s * STAGE_SZ;
#pragma unroll
            for (int i = 0; i < 12; i++)
                cpa16(base + dst[i], src[i] + (uint64_t)f * 128);
            CPA_COMMIT();
        }
    }

    MBAR_WAIT(smb + SM_FIN, 0);
    TC_FENCE_AFTER();

    // epilogue: warps 0-7 read TMEM (warp w -> subpartition w&3, disjoint cols)
    if (wid < 8) {
        int sub = wid & 3;
        size_t slot = row0 + sub * 32 + lane;
        if (mode) {
            int cbase = (wid >> 2) * 2;
#pragma unroll
            for (int cc = 0; cc < 2; cc++) {
                int ch = cbase + cc;
                uint32_t gr[32], ur[32];
                TCLD32(gr, tmem + ch * 32);          // gate panels 0-3
                TCLD32(ur, tmem + 128 + ch * 32);    // up panels 4-7
                TC_WAIT_LD();
                size_t ob = slot * 2048 + (size_t)cb * 128 + ch * 32;
                uint32_t hw[16], lw[16];
#pragma unroll
                for (int j = 0; j < 32; j += 2) {
                    float g0 = __uint_as_float(gr[j]);
                    float u0 = __uint_as_float(ur[j]);
                    float g1 = __uint_as_float(gr[j + 1]);
                    float u1 = __uint_as_float(ur[j + 1]);
                    float v0 = (g0 / (1.f + __expf(-g0))) * u0;
                    float v1 = (g1 / (1.f + __expf(-g1))) * u1;
                    hw[j >> 1] = prmt_hi(__float_as_uint(v0), __float_as_uint(v1));
                    lw[j >> 1] = bf2(losub(v1), losub(v0));
                }
#pragma unroll
                for (int q = 0; q < 4; q++) {
                    ((uint4*)&g_ih[ob])[q] = make_uint4(hw[q*4], hw[q*4+1], hw[q*4+2], hw[q*4+3]);
                    ((uint4*)&g_il[ob])[q] = make_uint4(lw[q*4], lw[q*4+1], lw[q*4+2], lw[q*4+3]);
                }
            }
        } else {
            int cbase = (wid >> 2) * 4;
#pragma unroll
            for (int cc = 0; cc < 4; cc++) {
                int ch = cbase + cc;
                uint32_t dr[32];
                TCLD32(dr, tmem + ch * 32);
                TC_WAIT_LD();
                float* op = &g_y[slot * 2048 + (size_t)cb * 256 + ch * 32];
#pragma unroll
                for (int j = 0; j < 32; j += 4) {
                    float4 o;
#pragma unroll
                    for (int q = 0; q < 4; q++)
                        ((float*)&o)[q] = __uint_as_float(dr[j + q]);
                    *(float4*)(op + j) = o;
                }
            }
        }
    }
    __syncthreads();
    if (wid == 0) TC_DEALLOC(tmem, 256);
#endif // HAS_TC
}

// ---------------- 4c) checker: verify tc GEMM1 (reads g_ih/g_il) -------------
__global__ void check_kernel(const float* __restrict__ X, const float* __restrict__ W1)
{
    int lane = threadIdx.x;
    int e = g_tile_expert[0];
    int tok = g_perm[0];
    float ga = 0.f, ua = 0.f, gb = 0.f, ub = 0.f;
    const float* xr = X + (size_t)tok * HID;
    const float* wb = W1 + (size_t)e * HID * 4096;
    for (int k = lane; k < HID; k += 32) {
        float x = xr[k];
        const float* wr = wb + (size_t)k * 4096;
        ga += x * wr[0];    ua += x * wr[2048];
        gb += x * wr[1];    ub += x * wr[2049];
    }
#pragma unroll
    for (int o = 16; o; o >>= 1) {
        ga += __shfl_xor_sync(0xffffffffu, ga, o);
        ua += __shfl_xor_sync(0xffffffffu, ua, o);
        gb += __shfl_xor_sync(0xffffffffu, gb, o);
        ub += __shfl_xor_sync(0xffffffffu, ub, o);
    }
    if (lane == 0) {
        float ea = (ga / (1.f + expf(-ga))) * ua;
        float eb = (gb / (1.f + expf(-gb))) * ub;
        float va = __uint_as_float((uint32_t)g_ih[0] << 16)
                 + __uint_as_float((uint32_t)g_il[0] << 16);
        float vb = __uint_as_float((uint32_t)g_ih[1] << 16)
                 + __uint_as_float((uint32_t)g_il[1] << 16);
        float ra = fabsf(va - ea) / fmaxf(fabsf(ea), 0.05f);
        float rb = fabsf(vb - eb) / fmaxf(fabsf(eb), 0.05f);
        int d;
        if (!g_tc_ran) d = 2;
        else if (ra < 0.02f && rb < 0.02f) d = 0;
        else if (va == 0.f && vb == 0.f) d = 3;
        else d = 1;
        g_diag = d;
    }
}

__global__ void diag_delay_kernel()
{
    int d = g_diag;
    if (d == 0) return;
    long long t0 = clock64();
    long long lim = (long long)d * 600000;
    while (clock64() - t0 < lim) { }
}

// ---------------- 4b) fallback mma.sync GEMM (runs iff g_diag != 0) ----------
#define BM 128
#define BN 128
#define BKK 16
#define AST 20
#define BST 136

__global__ __launch_bounds__(256, 2) void moe_gemm_fb(
    const float* __restrict__ Apar, const float* __restrict__ Ball,
    int N, int mode)
{
    if (g_diag == 0) return;
    int tile = blockIdx.y;
    int e = g_tile_expert[tile];
    if (e < 0) return;
    const float* A = mode ? Apar : g_inter;
    float* C = mode ? g_fc1 : g_y;
    const float* B = Ball + (size_t)e * HID * N;
    int row0 = tile * BM;
    int col0 = blockIdx.x * BN;
    int t = threadIdx.x;

    __shared__ __align__(16) float As[2][BM * AST];
    __shared__ __align__(16) float Bs[2][BKK * BST];
    __shared__ int prow[BM];
    if (t < BM) prow[t] = mode ? g_perm[row0 + t] : (row0 + t);
    __syncthreads();

    {
#pragma unroll
        for (int i = 0; i < 2; i++) {
            int lin = t + i * 256;
            int m = lin >> 2, kq = lin & 3;
            cp16g(&As[0][m * AST + kq * 4], A + (size_t)prow[m] * HID + kq * 4);
        }
#pragma unroll
        for (int i = 0; i < 2; i++) {
            int lin = t + i * 256;
            int k = lin >> 5, nq = lin & 31;
            cp16g(&Bs[0][k * BST + nq * 4], B + (size_t)k * N + col0 + nq * 4);
        }
        asm volatile("cp.async.commit_group;\n");
    }

    int wid = t >> 5, lane = t & 31;
    int wm = wid & 3, wn = wid >> 2;
    int gid = lane >> 2, tig = lane & 3;

    float acc[2][8][4];
#pragma unroll
    for (int a = 0; a < 2; a++)
#pragma unroll
        for (int b = 0; b < 8; b++)
#pragma unroll
            for (int c2 = 0; c2 < 4; c2++) acc[a][b][c2] = 0.f;

    const int NITF = HID / BKK;
    for (int it = 0; it < NITF; it++) {
        int st = it & 1;
        asm volatile("cp.async.wait_group 0;\n");
        __syncthreads();
        if (it + 1 < NITF) {
            int kk = (it + 1) * BKK;
            int s2 = st ^ 1;
#pragma unroll
            for (int i = 0; i < 2; i++) {
                int lin = t + i * 256;
                int m = lin >> 2, kq = lin & 3;
                cp16g(&As[s2][m * AST + kq * 4], A + (size_t)prow[m] * HID + kk + kq * 4);
            }
#pragma unroll
            for (int i = 0; i < 2; i++) {
                int lin = t + i * 256;
                int k = lin >> 5, nq = lin & 31;
                cp16g(&Bs[s2][k * BST + nq * 4], B + (size_t)(kk + k) * N + col0 + nq * 4);
            }
            asm volatile("cp.async.commit_group;\n");
        }
#pragma unroll
        for (int ks = 0; ks < BKK; ks += 8) {
            uint32_t af[2][4];
#pragma unroll
            for (int mf = 0; mf < 2; mf++) {
                int m = wm * 32 + mf * 16;
                af[mf][0] = f2tf(As[st][(m + gid)     * AST + ks + tig]);
                af[mf][1] = f2tf(As[st][(m + gid + 8) * AST + ks + tig]);
                af[mf][2] = f2tf(As[st][(m + gid)     * AST + ks + tig + 4]);
                af[mf][3] = f2tf(As[st][(m + gid + 8) * AST + ks + tig + 4]);
            }
            uint32_t bf[8][2];
#pragma unroll
            for (int nf = 0; nf < 8; nf++) {
                int n = wn * 64 + nf * 8 + gid;
                bf[nf][0] = f2tf(Bs[st][(ks + tig)     * BST + n]);
                bf[nf][1] = f2tf(Bs[st][(ks + tig + 4) * BST + n]);
            }
#pragma unroll
            for (int mf = 0; mf < 2; mf++)
#pragma unroll
                for (int nf = 0; nf < 8; nf++)
                    asm volatile(
                        "mma.sync.aligned.m16n8k8.row.col.f32.tf32.tf32.f32 "
                        "{%0,%1,%2,%3},{%4,%5,%6,%7},{%8,%9},{%0,%1,%2,%3};"
                        : "+f"(acc[mf][nf][0]), "+f"(acc[mf][nf][1]),
                          "+f"(acc[mf][nf][2]), "+f"(acc[mf][nf][3])
                        : "r"(af[mf][0]), "r"(af[mf][1]), "r"(af[mf][2]), "r"(af[mf][3]),
                          "r"(bf[nf][0]), "r"(bf[nf][1]));
        }
        __syncthreads();
    }

#pragma unroll
    for (int mf = 0; mf < 2; mf++) {
        int r = row0 + wm * 32 + mf * 16 + gid;
#pragma unroll
        for (int nf = 0; nf < 8; nf++) {
            int c = col0 + wn * 64 + nf * 8 + tig * 2;
            *(float2*)&C[(size_t)r * N + c] = make_float2(acc[mf][nf][0], acc[mf][nf][1]);
            *(float2*)&C[(size_t)(r + 8) * N + c] = make_float2(acc[mf][nf][2], acc[mf][nf][3]);
        }
    }
}

// ---------------- 5) GLU (fallback path only) --------------------------------
__global__ void glu_kernel()
{
    if (g_diag == 0) return;
    size_t idx = (size_t)blockIdx.x * 256 + threadIdx.x;
    size_t r = idx >> 11;
    int f = (int)(idx & 2047);
    float g = g_fc1[r * 4096 + f];
    float u = g_fc1[r * 4096 + 2048 + f];
    g_inter[idx] = (g / (1.f + expf(-g))) * u;
}

// ---------------- 6) combine -------------------------------------------------
__global__ void combine_kernel(float* __restrict__ out)
{
    int s = blockIdx.x;
    float s0 = g_score[2 * s], s1 = g_score[2 * s + 1];
    size_t a = (size_t)g_slotmap[2 * s] * 2048;
    size_t b = (size_t)g_slotmap[2 * s + 1] * 2048;
    for (int i = threadIdx.x * 4; i < 2048; i += 256 * 4) {
        float4 ya = *(const float4*)&g_y[a + i];
        float4 yb = *(const float4*)&g_y[b + i];
        float4 o;
        o.x = s0 * ya.x + s1 * yb.x; o.y = s0 * ya.y + s1 * yb.y;
        o.z = s0 * ya.z + s1 * yb.z; o.w = s0 * ya.w + s1 * yb.w;
        *(float4*)&out[(size_t)s * 2048 + i] = o;
    }
}

// ---------------- launch -----------------------------------------------------
extern "C" void kernel_launch(void* const* d_in, const int* in_sizes, int n_in,
                              void* d_out, int out_size)
{
    const float* X    = (const float*)d_in[0];
    const float* Wqkv = (const float*)d_in[1];
    const float* W1   = (const float*)d_in[2];
    const float* W2   = (const float*)d_in[3];
    float* out = (float*)d_out;

    cudaFuncSetAttribute(moe_gemm_tc, cudaFuncAttributeMaxDynamicSharedMemorySize, SM_TOTAL);

    // operand pre-conversion (bf16 hi/lo; W transposed to [e][n][k])
    convx_kernel<<<(S_TOK * HID / 4) / 256, 256>>>(X);
    convw_kernel<<<dim3(128, 64, NE), 256>>>(W1, g_w1h, g_w1l, 4096);
    convw_kernel<<<dim3(64, 64, NE), 256>>>(W2, g_w2h, g_w2l, 2048);

    gate_kernel<<<16, 256>>>(X, Wqkv);
    route_kernel<<<8, 256>>>();
    scatter_kernel<<<1, 256>>>();

    // tc GEMM1 (+fused GLU -> bf16 hi/lo), then numeric verification
    moe_gemm_tc<<<dim3(NTILES, 16), TCTHREADS, SM_TOTAL>>>(4096, 1, 0);
    check_kernel<<<1, 32>>>(X, W1);
    diag_delay_kernel<<<1, 1>>>();
    // fallback (only if tc failed verification)
    moe_gemm_fb<<<dim3(32, NTILES), 256>>>(X, W1, 4096, 1);
    glu_kernel<<<(MAXROWS * 2048) / 256, 256>>>();
    // GEMM2: tc if verified, else fallback
    moe_gemm_tc<<<dim3(NTILES, 8), TCTHREADS, SM_TOTAL>>>(2048, 0, 1);
    moe_gemm_fb<<<dim3(16, NTILES), 256>>>(nullptr, W2, 2048, 0);
    combine_kernel<<<S_TOK, 256>>>(out);
}

// round 17
// speedup vs baseline: 4.6554x; 4.6554x over previous
#include <cuda_runtime.h>
#include <cstdint>
#include <math.h>

#define S_TOK 2048
#define HID   2048
#define NJ    24
#define NE    8
#define MAXROWS 5120
#define NTILES  40

#if defined(__CUDA_ARCH__) && defined(__CUDA_ARCH_FEAT_SM103_ALL)
#define HAS_TC 1
#else
#define HAS_TC 0
#endif

// tcgen05 GEMM config: bf16 hi/lo split, KC=64 fp32 per stage, 2 stages
#define KC 64
#define NIT (HID / KC)        // 32
#define OFF_AH 0
#define OFF_AL 16384
#define OFF_BH 32768
#define OFF_BL 65536
#define STAGE_SZ 98304        // 96KB
#define SM_CTRL    (2 * STAGE_SZ)      // 196608
#define SM_TMEMPTR (SM_CTRL)
#define SM_DONE    (SM_CTRL + 16)      // 2 x 8B
#define SM_FIN     (SM_CTRL + 32)
#define SM_TOTAL   (SM_CTRL + 64)
#define TCTHREADS 512

// ---------------- device scratch ---------------------------------------------
__device__ float g_mix[S_TOK * NJ];
__device__ int   g_idx[S_TOK * 2];
__device__ float g_score[S_TOK * 2];
__device__ int   g_perm[MAXROWS];
__device__ int   g_slotmap[S_TOK * 2];
__device__ int   g_tile_expert[48];
__device__ int   g_tc_ran;
__device__ int   g_diag;              // 0 tc-ok | 1 wrong | 2 not-ran | 3 zeros
__device__ __align__(256) float g_fc1[(size_t)MAXROWS * 4096];
__device__ __align__(256) float g_inter[(size_t)MAXROWS * 2048];
__device__ __align__(256) float g_y[(size_t)MAXROWS * 2048];

// ---------------- generic helpers --------------------------------------------
__device__ __forceinline__ uint32_t f2tf(float f) {
    uint32_t u; asm("cvt.rna.tf32.f32 %0, %1;" : "=r"(u) : "f"(f)); return u;
}
__device__ __forceinline__ void cp16g(float* dst, const float* src) {
    uint32_t d = (uint32_t)__cvta_generic_to_shared(dst);
    asm volatile("cp.async.cg.shared.global [%0], [%1], 16;\n" :: "r"(d), "l"(src));
}
#define SWZ128(b) ((b) ^ (((b) >> 3) & 0x70))
__device__ __forceinline__ uint32_t prmt_hi(uint32_t a, uint32_t b) {
    uint32_t d; asm("prmt.b32 %0, %1, %2, 0x7632;" : "=r"(d) : "r"(a), "r"(b)); return d;
}
__device__ __forceinline__ float losub(float x) {   // exact residual of truncation
    return x - __uint_as_float(__float_as_uint(x) & 0xFFFF0000u);
}
__device__ __forceinline__ uint32_t bf2(float hi, float lo) {
    uint32_t d; asm("cvt.rn.bf16x2.f32 %0, %1, %2;" : "=r"(d) : "f"(hi), "f"(lo)); return d;
}
__device__ __forceinline__ void sts64s(uint32_t a, uint32_t x, uint32_t y) {
    asm volatile("st.shared.v2.b32 [%0], {%1,%2};" :: "r"(a), "r"(x), "r"(y));
}
__device__ __forceinline__ void sts128s(uint32_t a, uint32_t x, uint32_t y, uint32_t z, uint32_t w) {
    asm volatile("st.shared.v4.b32 [%0], {%1,%2,%3,%4};" :: "r"(a), "r"(x), "r"(y), "r"(z), "r"(w));
}

#if HAS_TC
__device__ __forceinline__ uint32_t smem_u32(const void* p) {
    uint32_t a;
    asm("{ .reg .u64 t; cvta.to.shared.u64 t, %1; cvt.u32.u64 %0, t; }" : "=r"(a) : "l"(p));
    return a;
}
__device__ __forceinline__ uint32_t elect_one() {
    uint32_t p;
    asm volatile("{\n\t.reg .pred p;\n\telect.sync _|p, 0xFFFFFFFF;\n\t"
                 "selp.b32 %0, 1, 0, p;\n\t}" : "=r"(p));
    return p;
}
// K-major SW128 descriptor (verified: test_mma / test_2cta / test_mma_iter)
static __device__ __forceinline__ uint64_t desc_k(uint32_t addr) {
    return ((uint64_t)2 << 61) | ((uint64_t)1 << 46) | ((uint64_t)64 << 32)
         | ((uint64_t)1 << 16) | (uint64_t)((addr >> 4) & 0x3FFF);
}
// VERIFIED idesc (test_mma.cu): F32 acc, bf16 x bf16, M=128, N=32
#define IDESC_BF16 0x8080490u

__device__ __forceinline__ void mma_bf16_ss(uint32_t d, uint64_t ad, uint64_t bd, uint32_t en) {
    asm volatile(
        "{\n\t.reg .pred p;\n\tsetp.ne.u32 p, %4, 0;\n\t"
        "tcgen05.mma.cta_group::1.kind::f16 [%0], %1, %2, %3, {%5, %5, %5, %5}, p;\n\t}"
        :: "r"(d), "l"(ad), "l"(bd), "r"(IDESC_BF16), "r"(en), "r"(0u) : "memory");
}
#define TC_ALLOC(sm, n)  asm volatile("tcgen05.alloc.cta_group::1.sync.aligned.shared::cta.b32 [%0], %1;" :: "r"(sm), "r"(n) : "memory")
#define TC_DEALLOC(t, n) asm volatile("tcgen05.dealloc.cta_group::1.sync.aligned.b32 %0, %1;" :: "r"(t), "r"(n))
#define TC_RELINQ()      asm volatile("tcgen05.relinquish_alloc_permit.cta_group::1.sync.aligned;")
#define TC_COMMIT(mb)    asm volatile("tcgen05.commit.cta_group::1.mbarrier::arrive::one.shared::cluster.b64 [%0];" :: "r"(mb) : "memory")
#define TC_FENCE_AFTER() asm volatile("tcgen05.fence::after_thread_sync;" ::: "memory")
#define TC_WAIT_LD()     asm volatile("tcgen05.wait::ld.sync.aligned;" ::: "memory")
#define FENCE_ASYNC()    asm volatile("fence.proxy.async.shared::cta;" ::: "memory")
#define MBAR_INIT(mb, c) asm volatile("mbarrier.init.shared.b64 [%0], %1;" :: "r"(mb), "r"(c) : "memory")

#define MBAR_WAIT(mb, par) do {                                                  \
    uint32_t _m = (mb), _p = (par), _d = 0;                                      \
    for (int _i = 0; _i < (1 << 22); _i++) {                                     \
        asm volatile("{\n\t.reg .pred p;\n\t"                                    \
            "mbarrier.try_wait.parity.acquire.cta.shared::cta.b64 p, [%1], %2;\n\t" \
            "selp.b32 %0, 1, 0, p;\n\t}" : "=r"(_d) : "r"(_m), "r"(_p) : "memory"); \
        if (_d) break;                                                           \
    }                                                                            \
} while (0)

#define TCLD32(r, a)                                                             \
    asm volatile("tcgen05.ld.sync.aligned.32x32b.x32.b32 "                       \
        "{%0,%1,%2,%3,%4,%5,%6,%7,%8,%9,%10,%11,%12,%13,%14,%15,"                \
        "%16,%17,%18,%19,%20,%21,%22,%23,%24,%25,%26,%27,%28,%29,%30,%31}, [%32];" \
        : "=r"((r)[0]),"=r"((r)[1]),"=r"((r)[2]),"=r"((r)[3]),"=r"((r)[4]),      \
          "=r"((r)[5]),"=r"((r)[6]),"=r"((r)[7]),"=r"((r)[8]),"=r"((r)[9]),      \
          "=r"((r)[10]),"=r"((r)[11]),"=r"((r)[12]),"=r"((r)[13]),"=r"((r)[14]), \
          "=r"((r)[15]),"=r"((r)[16]),"=r"((r)[17]),"=r"((r)[18]),"=r"((r)[19]), \
          "=r"((r)[20]),"=r"((r)[21]),"=r"((r)[22]),"=r"((r)[23]),"=r"((r)[24]), \
          "=r"((r)[25]),"=r"((r)[26]),"=r"((r)[27]),"=r"((r)[28]),"=r"((r)[29]), \
          "=r"((r)[30]),"=r"((r)[31]) : "r"(a))
#endif // HAS_TC

// ---------------- 1) router mix = X @ Wqkv^T (64 blocks x 32 tokens) ---------
__global__ __launch_bounds__(256) void gate_kernel(
    const float* __restrict__ X, const float* __restrict__ Wqkv)
{
    __shared__ float xs[32 * 17];
    __shared__ float ws[NJ * 17];
    int t = threadIdx.x;
    int tok0 = blockIdx.x * 32;
    int tok = t & 31;          // token within block
    int jgrp = t >> 5;         // 0..7 -> 3 j's each
    int j0 = jgrp * 3;

    float acc[3] = {0.f, 0.f, 0.f};

    for (int kc = 0; kc < HID; kc += 16) {
        for (int lin = t; lin < 32 * 16; lin += 256) {
            int m = lin >> 4, k = lin & 15;
            xs[m * 17 + k] = X[(size_t)(tok0 + m) * HID + kc + k];
        }
        for (int lin = t; lin < NJ * 16; lin += 256) {
            int j = lin >> 4, k = lin & 15;
            ws[j * 17 + k] = Wqkv[(size_t)j * HID + kc + k];
        }
        __syncthreads();
#pragma unroll
        for (int k = 0; k < 16; k++) {
            float xv = xs[tok * 17 + k];
            acc[0] += xv * ws[(j0 + 0) * 17 + k];
            acc[1] += xv * ws[(j0 + 1) * 17 + k];
            acc[2] += xv * ws[(j0 + 2) * 17 + k];
        }
        __syncthreads();
    }
#pragma unroll
    for (int j = 0; j < 3; j++)
        g_mix[(tok0 + tok) * NJ + j0 + j] = acc[j];
}

// ---------------- 2) router attention + top-2 --------------------------------
__global__ void route_kernel()
{
    int s = blockIdx.x * blockDim.x + threadIdx.x;
    if (s >= S_TOK) return;
    float q[NE], kk[NE], v[NE];
#pragma unroll
    for (int i = 0; i < NE; i++) {
        q[i] = g_mix[s * NJ + i]; kk[i] = g_mix[s * NJ + 8 + i]; v[i] = g_mix[s * NJ + 16 + i];
    }
    float logit[NE];
#pragma unroll
    for (int i = 0; i < NE; i++) {
        float mx = -1e30f;
#pragma unroll
        for (int j = 0; j < NE; j++) mx = fmaxf(mx, q[i] * kk[j]);
        float se = 0.f, ac = 0.f;
#pragma unroll
        for (int j = 0; j < NE; j++) {
            float e = expf(q[i] * kk[j] - mx);
            se += e; ac += e * v[j];
        }
        logit[i] = ac / se;
    }
    int i0 = 0;
#pragma unroll
    for (int j = 1; j < NE; j++) if (logit[j] > logit[i0]) i0 = j;
    int i1 = -1;
#pragma unroll
    for (int j = 0; j < NE; j++) {
        if (j == i0) continue;
        if (i1 < 0 || logit[j] > logit[i1]) i1 = j;
    }
    float e1 = expf(logit[i1] - logit[i0]);
    float p0 = 1.f / (1.f + e1);
    g_idx[2 * s] = i0; g_idx[2 * s + 1] = i1;
    g_score[2 * s] = p0; g_score[2 * s + 1] = e1 * p0;
}

// ---------------- 3) stable scatter ------------------------------------------
__global__ void scatter_kernel()
{
    __shared__ int cnt[NE];
    __shared__ int off[NE];
    int t = threadIdx.x, warp = t >> 5, lane = t & 31;

    for (int i = t; i < MAXROWS; i += 256) g_perm[i] = 0;
    if (t < 48) g_tile_expert[t] = -1;
    __syncthreads();

    int c = 0;
    for (int b = 0; b < S_TOK; b += 32) {
        int s = b + lane;
        bool m = (g_idx[2 * s] == warp) || (g_idx[2 * s + 1] == warp);
        c += __popc(__ballot_sync(0xffffffffu, m));
    }
    if (lane == 0) cnt[warp] = c;
    __syncthreads();

    if (t == 0) {
        int rb = 0, tb = 0;
        for (int e = 0; e < NE; e++) {
            off[e] = rb;
            int nt = (cnt[e] + 127) >> 7;
            for (int i = 0; i < nt; i++) g_tile_expert[tb++] = e;
            rb += nt << 7;
        }
    }
    __syncthreads();

    int base = off[warp];
    for (int b = 0; b < S_TOK; b += 32) {
        int s = b + lane;
        bool m0 = (g_idx[2 * s] == warp), m1 = (g_idx[2 * s + 1] == warp);
        bool m = m0 || m1;
        unsigned bal = __ballot_sync(0xffffffffu, m);
        if (m) {
            int pos = base + __popc(bal & ((1u << lane) - 1u));
            g_perm[pos] = s;
            g_slotmap[2 * s + (m0 ? 0 : 1)] = pos;
        }
        base += __popc(bal);
    }
}

// ---------------- 4a) tcgen05 grouped GEMM, bf16 hi/lo split, 512 thr --------
// mode=1: A = X via g_perm, B = W1 gate+up, fused GLU -> g_inter (fp32)
// mode=0: A = g_inter, B = W2 -> g_y
__global__ __launch_bounds__(TCTHREADS, 1) __cluster_dims__(1, 1, 1) void moe_gemm_tc(
    const float* __restrict__ Aglob, const float* __restrict__ Ball,
    int N, int mode, int guarded)
{
#if HAS_TC
    if (guarded && g_diag != 0) return;
    int tile = blockIdx.x;
    int e = g_tile_expert[tile];
    if (tile == 0 && blockIdx.y == 0 && threadIdx.x == 0 && mode) g_tc_ran = 1;
    if (e < 0) return;
    int cb = blockIdx.y;
    int row0 = tile * 128;
    const float* A = mode ? Aglob : g_inter;
    const float* B = Ball + (size_t)e * HID * N;
    int t = threadIdx.x, wid = t >> 5, lane = t & 31;

    extern __shared__ __align__(1024) char smem[];
    uint32_t smb = smem_u32(smem);

    if (t == 0) {
        MBAR_INIT(smb + SM_DONE + 0, 1);
        MBAR_INIT(smb + SM_DONE + 8, 1);
        MBAR_INIT(smb + SM_FIN, 1);
    }
    if (wid == 0) { TC_ALLOC(smb + SM_TMEMPTR, 256); TC_RELINQ(); }
    __syncthreads();
    uint32_t tmem;
    asm volatile("ld.shared.b32 %0, [%1];" : "=r"(tmem) : "r"(smb + SM_TMEMPTR));

    // ---- per-thread fill state (512 threads) ----
    const float* asrc[4]; uint32_t adst[4];
#pragma unroll
    for (int i = 0; i < 4; i++) {
        int id = t + i * TCTHREADS;
        int m = id >> 4, kq = id & 15;
        int r = mode ? __ldg(&g_perm[row0 + m]) : (row0 + m);
        asrc[i] = A + (size_t)r * HID + kq * 4;
        adst[i] = SWZ128((uint32_t)(m * 128 + kq * 8));
    }
    int p = wid & 7, half = wid >> 3;
    int colb = mode ? (p < 4 ? cb * 128 + p * 32 : 2048 + cb * 128 + (p - 4) * 32)
                    : (cb * 256 + p * 32);
    const float* bsrc = B + colb + lane;
    uint32_t bdst[4];
#pragma unroll
    for (int kg2 = 0; kg2 < 4; kg2++) {
        int kg = half * 4 + kg2;
        bdst[kg2] = p * 4096 + SWZ128((uint32_t)(lane * 128 + kg * 16));
    }

    // ---- fill: batched loads (break LDG->cvt chains), then convert+STS ------
    auto fill = [&](int f, int s) {
        uint32_t sb = smb + s * STAGE_SZ;
        size_t koff = (size_t)f * KC;
        // A: issue all 4 float4 loads first
        float4 av[4];
#pragma unroll
        for (int i = 0; i < 4; i++) av[i] = *(const float4*)(asrc[i] + koff);
#pragma unroll
        for (int i = 0; i < 4; i++) {
            uint32_t h01 = prmt_hi(__float_as_uint(av[i].x), __float_as_uint(av[i].y));
            uint32_t h23 = prmt_hi(__float_as_uint(av[i].z), __float_as_uint(av[i].w));
            uint32_t l01 = bf2(losub(av[i].y), losub(av[i].x));
            uint32_t l23 = bf2(losub(av[i].w), losub(av[i].z));
            sts64s(sb + OFF_AH + adst[i], h01, h23);
            sts64s(sb + OFF_AL + adst[i], l01, l23);
        }
        // B: two batches of 2 k-groups; each batch issues 16 loads up front
#pragma unroll
        for (int bb = 0; bb < 2; bb++) {
            float v[2][8];
#pragma unroll
            for (int kk = 0; kk < 2; kk++) {
                int kg = half * 4 + bb * 2 + kk;
                const float* pp = bsrc + (koff + kg * 8) * (size_t)N;
#pragma unroll
                for (int q = 0; q < 8; q++) v[kk][q] = __ldg(pp + q * (size_t)N);
            }
#pragma unroll
            for (int kk = 0; kk < 2; kk++) {
                int kg2 = bb * 2 + kk;
                uint32_t h0 = prmt_hi(__float_as_uint(v[kk][0]), __float_as_uint(v[kk][1]));
                uint32_t h1 = prmt_hi(__float_as_uint(v[kk][2]), __float_as_uint(v[kk][3]));
                uint32_t h2 = prmt_hi(__float_as_uint(v[kk][4]), __float_as_uint(v[kk][5]));
                uint32_t h3 = prmt_hi(__float_as_uint(v[kk][6]), __float_as_uint(v[kk][7]));
                uint32_t l0 = bf2(losub(v[kk][1]), losub(v[kk][0]));
                uint32_t l1 = bf2(losub(v[kk][3]), losub(v[kk][2]));
                uint32_t l2 = bf2(losub(v[kk][5]), losub(v[kk][4]));
                uint32_t l3 = bf2(losub(v[kk][7]), losub(v[kk][6]));
                sts128s(sb + OFF_BH + bdst[kg2], h0, h1, h2, h3);
                sts128s(sb + OFF_BL + bdst[kg2], l0, l1, l2, l3);
            }
        }
    };

    // prologue: chunk 0 -> buffer 0
    fill(0, 0);
    __syncthreads();

    for (int it = 0; it < NIT; it++) {
        int s = it & 1;
        if (wid == 0 && elect_one()) {
            FENCE_ASYNC();
            TC_FENCE_AFTER();
            uint32_t sb = smb + s * STAGE_SZ;
            uint64_t ah = desc_k(sb + OFF_AH), al = desc_k(sb + OFF_AL);
            uint64_t bh = desc_k(sb + OFF_BH), bl = desc_k(sb + OFF_BL);
#pragma unroll
            for (int pp = 0; pp < 8; pp++) {
                uint64_t bhp = bh + pp * 256, blp = bl + pp * 256;
#pragma unroll
                for (int k = 0; k < 4; k++)
                    mma_bf16_ss(tmem + pp * 32, ah + k * 2, bhp + k * 2, (it > 0) || (k > 0));
#pragma unroll
                for (int k = 0; k < 4; k++)
                    mma_bf16_ss(tmem + pp * 32, ah + k * 2, blp + k * 2, 1);
#pragma unroll
                for (int k = 0; k < 4; k++)
                    mma_bf16_ss(tmem + pp * 32, al + k * 2, bhp + k * 2, 1);
            }
            TC_COMMIT(smb + SM_DONE + 8 * s);
            if (it == NIT - 1) TC_COMMIT(smb + SM_FIN);
        }
        // prefetch chunk f = it+1 into the other buffer (overlaps MMA of chunk it)
        int f = it + 1;
        if (f < NIT) {
            int ns = f & 1;
            if (f >= 2) {
                if (t == 0) MBAR_WAIT(smb + SM_DONE + 8 * ns, ((f - 2) >> 1) & 1);
                __syncthreads();
            }
            fill(f, ns);
        }
        __syncthreads();
    }

    MBAR_WAIT(smb + SM_FIN, 0);
    TC_FENCE_AFTER();

    // epilogue: warps 0-7 read TMEM (warp w -> subpartition w&3, disjoint cols)
    if (wid < 8) {
        int sub = wid & 3;
        size_t slot = row0 + sub * 32 + lane;
        if (mode) {
            int cbase = (wid >> 2) * 2;
#pragma unroll
            for (int cc = 0; cc < 2; cc++) {
                int ch = cbase + cc;
                uint32_t gr[32], ur[32];
                TCLD32(gr, tmem + ch * 32);          // gate panels 0-3
                TCLD32(ur, tmem + 128 + ch * 32);    // up panels 4-7
                TC_WAIT_LD();
                float* op = &g_inter[slot * 2048 + (size_t)cb * 128 + ch * 32];
#pragma unroll
                for (int j = 0; j < 32; j += 4) {
                    float4 o;
#pragma unroll
                    for (int q = 0; q < 4; q++) {
                        float g0 = __uint_as_float(gr[j + q]);
                        float u0 = __uint_as_float(ur[j + q]);
                        ((float*)&o)[q] = (g0 / (1.f + __expf(-g0))) * u0;
                    }
                    *(float4*)(op + j) = o;
                }
            }
        } else {
            int cbase = (wid >> 2) * 4;
#pragma unroll
            for (int cc = 0; cc < 4; cc++) {
                int ch = cbase + cc;
                uint32_t dr[32];
                TCLD32(dr, tmem + ch * 32);
                TC_WAIT_LD();
                float* op = &g_y[slot * 2048 + (size_t)cb * 256 + ch * 32];
#pragma unroll
                for (int j = 0; j < 32; j += 4) {
                    float4 o;
#pragma unroll
                    for (int q = 0; q < 4; q++)
                        ((float*)&o)[q] = __uint_as_float(dr[j + q]);
                    *(float4*)(op + j) = o;
                }
            }
        }
    }
    __syncthreads();
    if (wid == 0) TC_DEALLOC(tmem, 256);
#endif // HAS_TC
}

// ---------------- 4c) checker ------------------------------------------------
__global__ void check_kernel(const float* __restrict__ X, const float* __restrict__ W1)
{
    int lane = threadIdx.x;
    int e = g_tile_expert[0];
    int tok = g_perm[0];
    float ga = 0.f, ua = 0.f, gb = 0.f, ub = 0.f;
    const float* xr = X + (size_t)tok * HID;
    const float* wb = W1 + (size_t)e * HID * 4096;
    for (int k = lane; k < HID; k += 32) {
        float x = xr[k];
        const float* wr = wb + (size_t)k * 4096;
        ga += x * wr[0];    ua += x * wr[2048];
        gb += x * wr[1];    ub += x * wr[2049];
    }
#pragma unroll
    for (int o = 16; o; o >>= 1) {
        ga += __shfl_xor_sync(0xffffffffu, ga, o);
        ua += __shfl_xor_sync(0xffffffffu, ua, o);
        gb += __shfl_xor_sync(0xffffffffu, gb, o);
        ub += __shfl_xor_sync(0xffffffffu, ub, o);
    }
    if (lane == 0) {
        float ea = (ga / (1.f + expf(-ga))) * ua;
        float eb = (gb / (1.f + expf(-gb))) * ub;
        float va = g_inter[0], vb = g_inter[1];
        float ra = fabsf(va - ea) / fmaxf(fabsf(ea), 0.05f);
        float rb = fabsf(vb - eb) / fmaxf(fabsf(eb), 0.05f);
        int d;
        if (!g_tc_ran) d = 2;
        else if (ra < 0.02f && rb < 0.02f) d = 0;
        else if (va == 0.f && vb == 0.f) d = 3;
        else d = 1;
        g_diag = d;
    }
}

__global__ void diag_delay_kernel()
{
    int d = g_diag;
    if (d == 0) return;
    long long t0 = clock64();
    long long lim = (long long)d * 600000;
    while (clock64() - t0 < lim) { }
}

// ---------------- 4b) fallback mma.sync GEMM (runs iff g_diag != 0) ----------
#define BM 128
#define BN 128
#define BKK 16
#define AST 20
#define BST 136

__global__ __launch_bounds__(256, 2) void moe_gemm_fb(
    const float* __restrict__ Apar, const float* __restrict__ Ball,
    int N, int mode)
{
    if (g_diag == 0) return;
    int tile = blockIdx.y;
    int e = g_tile_expert[tile];
    if (e < 0) return;
    const float* A = mode ? Apar : g_inter;
    float* C = mode ? g_fc1 : g_y;
    const float* B = Ball + (size_t)e * HID * N;
    int row0 = tile * BM;
    int col0 = blockIdx.x * BN;
    int t = threadIdx.x;

    __shared__ __align__(16) float As[2][BM * AST];
    __shared__ __align__(16) float Bs[2][BKK * BST];
    __shared__ int prow[BM];
    if (t < BM) prow[t] = mode ? g_perm[row0 + t] : (row0 + t);
    __syncthreads();

    {
#pragma unroll
        for (int i = 0; i < 2; i++) {
            int lin = t + i * 256;
            int m = lin >> 2, kq = lin & 3;
            cp16g(&As[0][m * AST + kq * 4], A + (size_t)prow[m] * HID + kq * 4);
        }
#pragma unroll
        for (int i = 0; i < 2; i++) {
            int lin = t + i * 256;
            int k = lin >> 5, nq = lin & 31;
            cp16g(&Bs[0][k * BST + nq * 4], B + (size_t)k * N + col0 + nq * 4);
        }
        asm volatile("cp.async.commit_group;\n");
    }

    int wid = t >> 5, lane = t & 31;
    int wm = wid & 3, wn = wid >> 2;
    int gid = lane >> 2, tig = lane & 3;

    float acc[2][8][4];
#pragma unroll
    for (int a = 0; a < 2; a++)
#pragma unroll
        for (int b = 0; b < 8; b++)
#pragma unroll
            for (int c2 = 0; c2 < 4; c2++) acc[a][b][c2] = 0.f;

    const int NITF = HID / BKK;
    for (int it = 0; it < NITF; it++) {
        int st = it & 1;
        asm volatile("cp.async.wait_group 0;\n");
        __syncthreads();
        if (it + 1 < NITF) {
            int kk = (it + 1) * BKK;
            int s2 = st ^ 1;
#pragma unroll
            for (int i = 0; i < 2; i++) {
                int lin = t + i * 256;
                int m = lin >> 2, kq = lin & 3;
                cp16g(&As[s2][m * AST + kq * 4], A + (size_t)prow[m] * HID + kk + kq * 4);
            }
#pragma unroll
            for (int i = 0; i < 2; i++) {
                int lin = t + i * 256;
                int k = lin >> 5, nq = lin & 31;
                cp16g(&Bs[s2][k * BST + nq * 4], B + (size_t)(kk + k) * N + col0 + nq * 4);
            }
            asm volatile("cp.async.commit_group;\n");
        }
#pragma unroll
        for (int ks = 0; ks < BKK; ks += 8) {
            uint32_t af[2][4];
#pragma unroll
            for (int mf = 0; mf < 2; mf++) {
                int m = wm * 32 + mf * 16;
                af[mf][0] = f2tf(As[st][(m + gid)     * AST + ks + tig]);
                af[mf][1] = f2tf(As[st][(m + gid + 8) * AST + ks + tig]);
                af[mf][2] = f2tf(As[st][(m + gid)     * AST + ks + tig + 4]);
                af[mf][3] = f2tf(As[st][(m + gid + 8) * AST + ks + tig + 4]);
            }
            uint32_t bf[8][2];
#pragma unroll
            for (int nf = 0; nf < 8; nf++) {
                int n = wn * 64 + nf * 8 + gid;
                bf[nf][0] = f2tf(Bs[st][(ks + tig)     * BST + n]);
                bf[nf][1] = f2tf(Bs[st][(ks + tig + 4) * BST + n]);
            }
#pragma unroll
            for (int mf = 0; mf < 2; mf++)
#pragma unroll
                for (int nf = 0; nf < 8; nf++)
                    asm volatile(
                        "mma.sync.aligned.m16n8k8.row.col.f32.tf32.tf32.f32 "
                        "{%0,%1,%2,%3},{%4,%5,%6,%7},{%8,%9},{%0,%1,%2,%3};"
                        : "+f"(acc[mf][nf][0]), "+f"(acc[mf][nf][1]),
                          "+f"(acc[mf][nf][2]), "+f"(acc[mf][nf][3])
                        : "r"(af[mf][0]), "r"(af[mf][1]), "r"(af[mf][2]), "r"(af[mf][3]),
                          "r"(bf[nf][0]), "r"(bf[nf][1]));
        }
        __syncthreads();
    }

#pragma unroll
    for (int mf = 0; mf < 2; mf++) {
        int r = row0 + wm * 32 + mf * 16 + gid;
#pragma unroll
        for (int nf = 0; nf < 8; nf++) {
            int c = col0 + wn * 64 + nf * 8 + tig * 2;
            *(float2*)&C[(size_t)r * N + c] = make_float2(acc[mf][nf][0], acc[mf][nf][1]);
            *(float2*)&C[(size_t)(r + 8) * N + c] = make_float2(acc[mf][nf][2], acc[mf][nf][3]);
        }
    }
}

// ---------------- 5) GLU (fallback path only) --------------------------------
__global__ void glu_kernel()
{
    if (g_diag == 0) return;
    size_t idx = (size_t)blockIdx.x * 256 + threadIdx.x;
    size_t r = idx >> 11;
    int f = (int)(idx & 2047);
    float g = g_fc1[r * 4096 + f];
    float u = g_fc1[r * 4096 + 2048 + f];
    g_inter[idx] = (g / (1.f + expf(-g))) * u;
}

// ---------------- 6) combine -------------------------------------------------
__global__ void combine_kernel(float* __restrict__ out)
{
    int s = blockIdx.x;
    float s0 = g_score[2 * s], s1 = g_score[2 * s + 1];
    size_t a = (size_t)g_slotmap[2 * s] * 2048;
    size_t b = (size_t)g_slotmap[2 * s + 1] * 2048;
    for (int i = threadIdx.x * 4; i < 2048; i += 256 * 4) {
        float4 ya = *(const float4*)&g_y[a + i];
        float4 yb = *(const float4*)&g_y[b + i];
        float4 o;
        o.x = s0 * ya.x + s1 * yb.x; o.y = s0 * ya.y + s1 * yb.y;
        o.z = s0 * ya.z + s1 * yb.z; o.w = s0 * ya.w + s1 * yb.w;
        *(float4*)&out[(size_t)s * 2048 + i] = o;
    }
}

// ---------------- launch -----------------------------------------------------
extern "C" void kernel_launch(void* const* d_in, const int* in_sizes, int n_in,
                              void* d_out, int out_size)
{
    const float* X    = (const float*)d_in[0];
    const float* Wqkv = (const float*)d_in[1];
    const float* W1   = (const float*)d_in[2];
    const float* W2   = (const float*)d_in[3];
    float* out = (float*)d_out;

    cudaFuncSetAttribute(moe_gemm_tc, cudaFuncAttributeMaxDynamicSharedMemorySize, SM_TOTAL);

    gate_kernel<<<64, 256>>>(X, Wqkv);
    route_kernel<<<8, 256>>>();
    scatter_kernel<<<1, 256>>>();
    // tc GEMM1 (+fused GLU), then numeric verification
    moe_gemm_tc<<<dim3(NTILES, 16), TCTHREADS, SM_TOTAL>>>(X, W1, 4096, 1, 0);
    check_kernel<<<1, 32>>>(X, W1);
    diag_delay_kernel<<<1, 1>>>();
    // fallback (only if tc failed verification)
    moe_gemm_fb<<<dim3(32, NTILES), 256>>>(X, W1, 4096, 1);
    glu_kernel<<<(MAXROWS * 2048) / 256, 256>>>();
    // GEMM2: tc if verified, else fallback
    moe_gemm_tc<<<dim3(NTILES, 8), TCTHREADS, SM_TOTAL>>>(nullptr, W2, 2048, 0, 1);
    moe_gemm_fb<<<dim3(16, NTILES), 256>>>(nullptr, W2, 2048, 0);
    combine_kernel<<<S_TOK, 256>>>(out);
}